// round 14
// baseline (speedup 1.0000x reference)
#include <cuda_runtime.h>
#include <cstdint>

#define Bb 16
#define Hh 256
#define Ww 256
#define Cc 64
#define M1m 20
#define M2m 20

// Scratch (device globals; no allocation allowed)
__device__ float2 g_A [Bb*Hh*M2m*Cc];   // forward w-transform   [b][h][ky][c]
__device__ float2 g_M [Bb*M2m*M1m*Cc];  // K2 partial (h-chunk 0)
__device__ float2 g_Mo[Bb*M2m*M1m*Cc];  // K2 partial (chunk 1) -> then mixed modes
__device__ float2 g_T [Bb*Hh*M2m*Cc];   // inverse h-expand      [b][h][ky][c]

#define TWO_PI_OVER_256 0.0245436926061702596f

// ---- f32x2 helpers ----------------------------------------------------------
__device__ __forceinline__ double ffma2(double a, double b, double c) {
    double d;
    asm("fma.rn.f32x2 %0, %1, %2, %3;" : "=d"(d) : "d"(a), "d"(b), "d"(c));
    return d;
}
__device__ __forceinline__ double add2(double a, double b) {
    double d;
    asm("add.rn.f32x2 %0, %1, %2;" : "=d"(d) : "d"(a), "d"(b));
    return d;
}
__device__ __forceinline__ double neg2(double a) {
    return __longlong_as_double(__double_as_longlong(a) ^ 0x8000000080000000ULL);
}
__device__ __forceinline__ double dup2(float x) {
    double d; asm("mov.b64 %0, {%1, %1};" : "=d"(d) : "f"(x)); return d;
}
__device__ __forceinline__ float2 up2(double d) {
    float2 f; asm("mov.b64 {%0, %1}, %2;" : "=f"(f.x), "=f"(f.y) : "d"(d));
    return f;
}
__device__ __forceinline__ uint32_t smem_u32(const void* p) {
    uint32_t a;
    asm("{ .reg .u64 t; cvta.to.shared.u64 t, %1; cvt.u32.u64 %0, t; }"
        : "=r"(a) : "l"(p));
    return a;
}
__device__ __forceinline__ void cp_async8(uint32_t dst, const void* src) {
    asm volatile("cp.async.ca.shared.global [%0], [%1], 8;"
                 :: "r"(dst), "l"(src) : "memory");
}
__device__ __forceinline__ void cp_async16(uint32_t dst, const void* src) {
    asm volatile("cp.async.cg.shared.global [%0], [%1], 16;"
                 :: "r"(dst), "l"(src) : "memory");
}

// ---------------------------------------------------------------------------
// K1: A[b,h,ky,c] = sum_w P*e^{-i ky w th}   (mod-4 radix fold over w)
// Fill: cp.async raw P (linear 64KB) into the 4 plane regions (raw rows
// 0-63 -> sS0, 64-127 -> sS2, 128-191 -> sDr, 192-255 -> sDi), then an
// exact in-place radix-4 butterfly (each thread owns its 4 slots).
// ---------------------------------------------------------------------------
__global__ void __launch_bounds__(320) k_fwd_w(const float* __restrict__ pts,
                                               int b0) {
    extern __shared__ float sm[];
    float*  sS0 = sm;                        // [64][64]
    float*  sS2 = sm + 4096;
    float*  sDr = sm + 8192;
    float*  sDi = sm + 12288;
    float2* tcs = (float2*)(sm + 16384);     // 256 x (cos, -sin)
    const int h = blockIdx.x, b = blockIdx.y + b0;
    const int tid = threadIdx.x;
    const float4* prow = (const float4*)(pts + ((size_t)(b*Hh + h))*(Ww*Cc));

    // fire-and-forget raw copy (linear: raw row order == region order)
    {
        const uint32_t smb = smem_u32(sm);
        for (int i = tid; i < 4096; i += 320)
            cp_async16(smb + (uint32_t)i*16u, prow + i);
        asm volatile("cp.async.commit_group;" ::: "memory");
    }
    if (tid < 256) {
        float s, c; sincosf((float)tid * TWO_PI_OVER_256, &s, &c);
        tcs[tid] = make_float2(c, -s);
    }
    asm volatile("cp.async.wait_group 0;" ::: "memory");
    __syncthreads();

    // in-place radix-4 butterfly (same arithmetic order as before)
    for (int i = tid; i < 1024; i += 320) {
        float4 a = ((const float4*)sS0)[i];
        float4 e = ((const float4*)sS2)[i];
        float4 c = ((const float4*)sDr)[i];
        float4 d = ((const float4*)sDi)[i];
        float4 pac = make_float4(a.x+c.x, a.y+c.y, a.z+c.z, a.w+c.w);
        float4 pbd = make_float4(e.x+d.x, e.y+d.y, e.z+d.z, e.w+d.w);
        ((float4*)sS0)[i] = make_float4(pac.x+pbd.x, pac.y+pbd.y,
                                        pac.z+pbd.z, pac.w+pbd.w);
        ((float4*)sS2)[i] = make_float4(pac.x-pbd.x, pac.y-pbd.y,
                                        pac.z-pbd.z, pac.w-pbd.w);
        ((float4*)sDr)[i] = make_float4(a.x-c.x, a.y-c.y, a.z-c.z, a.w-c.w);
        ((float4*)sDi)[i] = make_float4(e.x-d.x, e.y-d.y, e.z-d.z, e.w-d.w);
    }
    __syncthreads();

    const int ws = tid & 1;
    const int cg = (tid >> 1) & 7;
    const int idx = tid >> 4;                 // 0..19
    const int c0 = cg * 8;
    const int wbeg = ws * 32;

    float r[8], q[8];
    int ky;

    if (idx < 10) {                           // even ky class
        ky = 2 * idx;
        const float* plane = (ky & 2) ? sS2 : sS0;
        #pragma unroll
        for (int k = 0; k < 8; ++k) { r[k] = 0.f; q[k] = 0.f; }
        int t = (ky * wbeg) & 255;
        #pragma unroll 4
        for (int w = wbeg; w < wbeg + 32; ++w) {
            const float* pr = plane + w*64 + c0;
            float4 pA = *(const float4*)(pr);
            float4 pB = *(const float4*)(pr + 4);
            float2 cs = tcs[t];
            float cv = cs.x, ns = cs.y;
            r[0] += pA.x*cv; q[0] += pA.x*ns;
            r[1] += pA.y*cv; q[1] += pA.y*ns;
            r[2] += pA.z*cv; q[2] += pA.z*ns;
            r[3] += pA.w*cv; q[3] += pA.w*ns;
            r[4] += pB.x*cv; q[4] += pB.x*ns;
            r[5] += pB.y*cv; q[5] += pB.y*ns;
            r[6] += pB.z*cv; q[6] += pB.z*ns;
            r[7] += pB.w*cv; q[7] += pB.w*ns;
            t = (t + ky) & 255;
        }
    } else {                                  // odd ky class
        ky = 2 * (idx - 10) + 1;
        float xr[8], xs[8], yc[8], yn[8];
        #pragma unroll
        for (int k = 0; k < 8; ++k) { xr[k]=0.f; xs[k]=0.f; yc[k]=0.f; yn[k]=0.f; }
        int t = (ky * wbeg) & 255;
        #pragma unroll 2
        for (int w = wbeg; w < wbeg + 32; ++w) {
            const float* drp = sDr + w*64 + c0;
            const float* dip = sDi + w*64 + c0;
            float4 rA = *(const float4*)(drp);
            float4 rB = *(const float4*)(drp + 4);
            float4 iA = *(const float4*)(dip);
            float4 iB = *(const float4*)(dip + 4);
            float2 cs = tcs[t];
            float cv = cs.x, ns = cs.y;
            xr[0] += rA.x*cv; xs[0] += rA.x*ns; yc[0] += iA.x*cv; yn[0] += iA.x*ns;
            xr[1] += rA.y*cv; xs[1] += rA.y*ns; yc[1] += iA.y*cv; yn[1] += iA.y*ns;
            xr[2] += rA.z*cv; xs[2] += rA.z*ns; yc[2] += iA.z*cv; yn[2] += iA.z*ns;
            xr[3] += rA.w*cv; xs[3] += rA.w*ns; yc[3] += iA.w*cv; yn[3] += iA.w*ns;
            xr[4] += rB.x*cv; xs[4] += rB.x*ns; yc[4] += iB.x*cv; yn[4] += iB.x*ns;
            xr[5] += rB.y*cv; xs[5] += rB.y*ns; yc[5] += iB.y*cv; yn[5] += iB.y*ns;
            xr[6] += rB.z*cv; xs[6] += rB.z*ns; yc[6] += iB.z*cv; yn[6] += iB.z*ns;
            xr[7] += rB.w*cv; xs[7] += rB.w*ns; yc[7] += iB.w*cv; yn[7] += iB.w*ns;
            t = (t + ky) & 255;
        }
        const float s = ((ky & 3) == 1) ? -1.f : 1.f;
        #pragma unroll
        for (int k = 0; k < 8; ++k) {
            r[k] = xr[k] - s*yn[k];
            q[k] = xs[k] + s*yc[k];
        }
    }

    __syncthreads();
    if (ws == 1) {
        float* buf = sS0 + (ky*8 + cg)*16;
        #pragma unroll
        for (int k = 0; k < 8; ++k) { buf[k] = r[k]; buf[8+k] = q[k]; }
    }
    __syncthreads();
    if (ws == 0) {
        const float* buf = sS0 + (ky*8 + cg)*16;
        #pragma unroll
        for (int k = 0; k < 8; ++k) { r[k] += buf[k]; q[k] += buf[8+k]; }
        float2* dst = g_A + (((size_t)(b*Hh + h))*M2m + ky)*Cc + c0;
        #pragma unroll
        for (int k = 0; k < 4; ++k)
            *(float4*)(dst + 2*k) = make_float4(r[2*k], q[2*k], r[2*k+1], q[2*k+1]);
    }
}

// ---------------------------------------------------------------------------
// K2: M[b,ky,kx,c] = sum_h A*e^{-i(kx-10)h th}   (mod-2 fold, 2-way h split)
// [round-10 proven version]
// ---------------------------------------------------------------------------
#define HT2 32
__global__ void __launch_bounds__(128) k_fwd_h() {
    __shared__ float2 sAp[HT2*Cc];
    __shared__ float2 sAm[HT2*Cc];
    __shared__ float sCv[HT2*M1m];
    __shared__ float sSv[HT2*M1m];
    __shared__ float2 tbl[256];
    const int ky = blockIdx.x, b = blockIdx.y, hc = blockIdx.z;
    const int tid = threadIdx.x;
    for (int i = tid; i < 256; i += 128) {
        float s, c; sincosf((float)i * TWO_PI_OVER_256, &s, &c);
        tbl[i] = make_float2(c, s);
    }
    const int cc = tid & 63, kg = tid >> 6;
    double aar[5] = {0,0,0,0,0}, aai[5] = {0,0,0,0,0};
    __syncthreads();

    for (int h0 = hc*64; h0 < hc*64 + 64; h0 += HT2) {
        __syncthreads();
        for (int i = tid; i < HT2*Cc; i += 128) {
            int hh = i >> 6, c = i & 63;
            float2 a0 = g_A[(((size_t)(b*Hh + h0 + hh))*M2m + ky)*Cc + c];
            float2 a1 = g_A[(((size_t)(b*Hh + h0 + hh + 128))*M2m + ky)*Cc + c];
            sAp[i] = make_float2(a0.x + a1.x, a0.y + a1.y);
            sAm[i] = make_float2(a0.x - a1.x, a0.y - a1.y);
        }
        for (int i = tid; i < HT2*M1m; i += 128) {
            int hh = i / M1m, jj = i - hh*M1m;
            int kgg = jj / 10, j = jj - kgg*10;
            int kx = 2*j + kgg;
            float2 cs = tbl[((kx + 246) * (h0 + hh)) & 255];
            sCv[i] = cs.x; sSv[i] = cs.y;
        }
        __syncthreads();
        const float2* plane = kg ? sAm : sAp;
        #pragma unroll 2
        for (int hh = 0; hh < HT2; ++hh) {
            float2 a = plane[hh*Cc + cc];
            double dax = dup2(a.x), day = dup2(a.y), dnx = dup2(-a.x);
            const float* cvp = sCv + hh*M1m + kg*10;
            const float* svp = sSv + hh*M1m + kg*10;
            #pragma unroll
            for (int p = 0; p < 5; ++p) {
                double cp = *(const double*)(cvp + 2*p);
                double sp = *(const double*)(svp + 2*p);
                aar[p] = ffma2(dax, cp, aar[p]);
                aar[p] = ffma2(day, sp, aar[p]);
                aai[p] = ffma2(day, cp, aai[p]);
                aai[p] = ffma2(dnx, sp, aai[p]);
            }
        }
    }
    float2* gout = hc ? g_Mo : g_M;
    #pragma unroll
    for (int p = 0; p < 5; ++p) {
        float2 r = up2(aar[p]), im = up2(aai[p]);
        int kx0 = 4*p + kg;
        size_t base = (((size_t)(b*M2m + ky))*M1m)*Cc + cc;
        gout[base + (size_t)kx0*Cc]       = make_float2(r.x, im.x);
        gout[base + (size_t)(kx0+2)*Cc]   = make_float2(r.y, im.y);
    }
}

// ---------------------------------------------------------------------------
// K3: channel mix + alpha fold; input = g_M + g_Mo partials, output -> g_Mo
// grid (400, 2): blockIdx.y = batch half (8 batches each) -> 800 CTAs
// ---------------------------------------------------------------------------
__global__ void __launch_bounds__(256) k_mix(const float* __restrict__ kr,
                                             const float* __restrict__ ki) {
    __shared__ float sKr[64*65];
    __shared__ float sKi[64*65];
    __shared__ float2 sMin[8*64];
    const int kx = blockIdx.x / M2m, ky = blockIdx.x % M2m;
    const int bh = blockIdx.y;
    const int tid = threadIdx.x;
    const size_t kbase = ((size_t)(kx*M2m + ky))*Cc*Cc;
    for (int idx = tid; idx < 64*64; idx += 256) {
        int i = idx >> 6, j = idx & 63;
        sKr[i*65 + j] = kr[kbase + idx];
        sKi[i*65 + j] = ki[kbase + idx];
    }
    for (int idx = tid; idx < 8*64; idx += 256) {
        int bb = bh*8 + (idx >> 6), j = idx & 63;
        size_t gi = (((size_t)(bb*M2m + ky))*M1m + kx)*Cc + j;
        float2 m0 = g_M[gi], m1 = g_Mo[gi];
        sMin[idx] = make_float2(m0.x + m1.x, m0.y + m1.y);
    }
    __syncthreads();
    const float sc = (ky == 0 ? 1.0f : 2.0f) * (1.0f/65536.0f);
    const int i = tid & 63, bq = tid >> 6;
    float ar[2] = {0,0}, ai[2] = {0,0};
    for (int j = 0; j < 64; ++j) {
        float krv = sKr[i*65 + j], kiv = sKi[i*65 + j];
        #pragma unroll
        for (int r = 0; r < 2; ++r) {
            float2 m = sMin[(bq*2 + r)*64 + j];
            ar[r] += krv*m.x - kiv*m.y;
            ai[r] += krv*m.y + kiv*m.x;
        }
    }
    #pragma unroll
    for (int r = 0; r < 2; ++r) {
        int bb = bh*8 + bq*2 + r;
        g_Mo[(((size_t)(bb*M2m + ky))*M1m + kx)*Cc + i] =
            make_float2(ar[r]*sc, ai[r]*sc);
    }
}

// ---------------------------------------------------------------------------
// K4: T[b,h,ky,c] = sum_kx Mo*e^{+i(kx-10)h th}   (mod-2 fold over h)
// [round-10 proven version]
// ---------------------------------------------------------------------------
__global__ void __launch_bounds__(256) k_inv_h() {
    __shared__ float2 sMo[M1m*Cc];
    __shared__ float2 tA[256];
    __shared__ float2 tB[256];
    const int ky = blockIdx.x, b = blockIdx.y, hc = blockIdx.z;
    const int tid = threadIdx.x;
    {
        float s, c; sincosf((float)tid * TWO_PI_OVER_256, &s, &c);
        tA[tid] = make_float2(c, s);
        tB[tid] = make_float2(-s, c);
    }
    for (int i = tid; i < M1m*Cc; i += 256)
        sMo[i] = g_Mo[((size_t)(b*M2m + ky))*M1m*Cc + i];
    __syncthreads();
    const int cc = tid & 63, hg = tid >> 6;
    double dmr[M1m], dmi[M1m];
    #pragma unroll
    for (int kx = 0; kx < M1m; ++kx) {
        float2 m = sMo[kx*Cc + cc];
        dmr[kx] = dup2(m.x); dmi[kx] = dup2(m.y);
    }
    #pragma unroll 2
    for (int it = 0; it < 16; ++it) {
        int h = hc*64 + hg + 4*it;
        double ae = 0.0, ao = 0.0;
        int t = (246*h) & 255;
        #pragma unroll
        for (int kx = 0; kx < M1m; ++kx) {
            double ta = *(const double*)&tA[t];
            double tb = *(const double*)&tB[t];
            if (kx & 1) {
                ao = ffma2(dmr[kx], ta, ao);
                ao = ffma2(dmi[kx], tb, ao);
            } else {
                ae = ffma2(dmr[kx], ta, ae);
                ae = ffma2(dmi[kx], tb, ae);
            }
            t = (t + h) & 255;
        }
        float2 fe = up2(ae), fo = up2(ao);
        size_t base = (((size_t)(b*Hh + h))*M2m + ky)*Cc + cc;
        g_T[base]                       = make_float2(fe.x + fo.x, fe.y + fo.y);
        g_T[base + (size_t)128*M2m*Cc]  = make_float2(fe.x - fo.x, fe.y - fo.y);
    }
}

// ---------------------------------------------------------------------------
// K5: out[w,c] = spectral + P @ (Wl^T + I)   [round-13 proven: cp.async fill]
// ---------------------------------------------------------------------------
#define SPS 66
__global__ void __launch_bounds__(256, 2) k_final(const float* __restrict__ pts,
                                                  const float* __restrict__ wl,
                                                  float* __restrict__ out) {
    extern __shared__ float sm[];
    float*  sW  = sm;                        // [j][c] 64x64 (wl^T + I)
    float*  sTe = sm + 4096;                 // [10][128] even ky: Tr | -Ti
    float*  sTo = sTe + 1280;                // [10][128] odd ky
    float2* tcs = (float2*)(sTo + 1280);     // 256 (cos, sin)
    float*  sP  = (float*)(tcs + 256);       // [256][SPS]
    const int h = blockIdx.x, b = blockIdx.y;
    const int tid = threadIdx.x;
    const size_t rowbase = ((size_t)(b*Hh + h))*(Ww*Cc);

    // ---- sP fill via cp.async, issued first (no register dependency) ----
    {
        const float* srcbase = pts + rowbase;
        const uint32_t sPa = smem_u32(sP);
        for (int i = tid; i < 4096; i += 256) {
            int row = i >> 4, c4 = (i & 15) << 2;
            uint32_t dst = sPa + (uint32_t)(row*SPS + c4) * 4u;
            const float* src = srcbase + i*4;
            cp_async8(dst, src);
            cp_async8(dst + 8, src + 2);
        }
        asm volatile("cp.async.commit_group;" ::: "memory");
    }

    // ---- other fills (normal) ----
    for (int idx = tid; idx < Cc*Cc; idx += 256) {
        int c = idx >> 6, j = idx & 63;
        sW[j*64 + c] = wl[idx] + ((c == j) ? 1.0f : 0.0f);
    }
    {
        const float2* tsrc = g_T + ((size_t)(b*Hh + h))*M2m*Cc;
        for (int i = tid; i < M2m*Cc; i += 256) {
            int ky = i >> 6, c = i & 63;
            float2 v = tsrc[i];
            float* basep = (ky & 1) ? sTo : sTe;
            int e = ky >> 1;
            basep[e*128 + c]      = v.x;
            basep[e*128 + 64 + c] = -v.y;
        }
    }
    {
        float s, c; sincosf((float)tid * TWO_PI_OVER_256, &s, &c);
        tcs[tid] = make_float2(c, s);
    }
    __syncthreads();   // sTe/sTo/tcs/sW ready; sP still in flight

    const int cg = tid & 7, wpg = tid >> 3;
    const int c0 = cg * 8;
    const int wbase = wpg * 4;

    double acc[8][4];   // [k<4: rows wbase+k][4+k: +128 mirrors] x 4 c-pairs

    // ---- spectral (overlaps cp.async landing) ----
    #pragma unroll
    for (int pass = 0; pass < 2; ++pass) {
        const int wb0 = wbase + pass*2;
        double Re[2][4], Ro[2][4];
        #pragma unroll
        for (int pp = 0; pp < 2; ++pp)
            #pragma unroll
            for (int cp = 0; cp < 4; ++cp) { Re[pp][cp] = 0.0; Ro[pp][cp] = 0.0; }

        #pragma unroll
        for (int e = 0; e < 10; ++e) {          // even ky = 2e
            const float* row = sTe + e*128;
            double2 t0 = *(const double2*)(row + c0);
            double2 t1 = *(const double2*)(row + c0 + 4);
            double2 n0 = *(const double2*)(row + 64 + c0);
            double2 n1 = *(const double2*)(row + 68 + c0);
            #pragma unroll
            for (int pp = 0; pp < 2; ++pp) {
                float2 cs = tcs[(2*e*(wb0+pp)) & 255];
                double dc = dup2(cs.x), ds = dup2(cs.y);
                Re[pp][0] = ffma2(dc, t0.x, Re[pp][0]);
                Re[pp][1] = ffma2(dc, t0.y, Re[pp][1]);
                Re[pp][2] = ffma2(dc, t1.x, Re[pp][2]);
                Re[pp][3] = ffma2(dc, t1.y, Re[pp][3]);
                Re[pp][0] = ffma2(ds, n0.x, Re[pp][0]);
                Re[pp][1] = ffma2(ds, n0.y, Re[pp][1]);
                Re[pp][2] = ffma2(ds, n1.x, Re[pp][2]);
                Re[pp][3] = ffma2(ds, n1.y, Re[pp][3]);
            }
        }
        #pragma unroll
        for (int e = 0; e < 10; ++e) {          // odd ky = 2e+1
            const float* row = sTo + e*128;
            double2 t0 = *(const double2*)(row + c0);
            double2 t1 = *(const double2*)(row + c0 + 4);
            double2 n0 = *(const double2*)(row + 64 + c0);
            double2 n1 = *(const double2*)(row + 68 + c0);
            #pragma unroll
            for (int pp = 0; pp < 2; ++pp) {
                float2 cs = tcs[((2*e+1)*(wb0+pp)) & 255];
                double dc = dup2(cs.x), ds = dup2(cs.y);
                Ro[pp][0] = ffma2(dc, t0.x, Ro[pp][0]);
                Ro[pp][1] = ffma2(dc, t0.y, Ro[pp][1]);
                Ro[pp][2] = ffma2(dc, t1.x, Ro[pp][2]);
                Ro[pp][3] = ffma2(dc, t1.y, Ro[pp][3]);
                Ro[pp][0] = ffma2(ds, n0.x, Ro[pp][0]);
                Ro[pp][1] = ffma2(ds, n0.y, Ro[pp][1]);
                Ro[pp][2] = ffma2(ds, n1.x, Ro[pp][2]);
                Ro[pp][3] = ffma2(ds, n1.y, Ro[pp][3]);
            }
        }
        #pragma unroll
        for (int pp = 0; pp < 2; ++pp) {
            int k = pass*2 + pp;
            #pragma unroll
            for (int cp = 0; cp < 4; ++cp) {
                acc[k][cp]     = add2(Re[pp][cp], Ro[pp][cp]);
                acc[4 + k][cp] = add2(Re[pp][cp], neg2(Ro[pp][cp]));
            }
        }
    }

    // ---- wait for sP, then linear GEMM ----
    asm volatile("cp.async.wait_group 0;" ::: "memory");
    __syncthreads();

    #pragma unroll 2
    for (int j = 0; j < Cc; j += 2) {
        double2 B0a = *(const double2*)(sW + (j+0)*64 + c0);
        double2 B0b = *(const double2*)(sW + (j+0)*64 + c0 + 4);
        double2 B1a = *(const double2*)(sW + (j+1)*64 + c0);
        double2 B1b = *(const double2*)(sW + (j+1)*64 + c0 + 4);
        #pragma unroll
        for (int k = 0; k < 8; ++k) {
            int row = (k < 4) ? (wbase + k) : (wbase + k - 4 + 128);
            float2 p = *(const float2*)(sP + row*SPS + j);
            double d0 = dup2(p.x), d1 = dup2(p.y);
            acc[k][0] = ffma2(d0, B0a.x, acc[k][0]);
            acc[k][1] = ffma2(d0, B0a.y, acc[k][1]);
            acc[k][2] = ffma2(d0, B0b.x, acc[k][2]);
            acc[k][3] = ffma2(d0, B0b.y, acc[k][3]);
            acc[k][0] = ffma2(d1, B1a.x, acc[k][0]);
            acc[k][1] = ffma2(d1, B1a.y, acc[k][1]);
            acc[k][2] = ffma2(d1, B1b.x, acc[k][2]);
            acc[k][3] = ffma2(d1, B1b.y, acc[k][3]);
        }
    }

    // ---- store (double2 = packed float pairs, bit-exact layout) ----
    #pragma unroll
    for (int k = 0; k < 8; ++k) {
        int row = (k < 4) ? (wbase + k) : (wbase + k - 4 + 128);
        float* op = out + rowbase + (size_t)row*Cc + c0;
        *(double2*)(op)     = make_double2(acc[k][0], acc[k][1]);
        *(double2*)(op + 4) = make_double2(acc[k][2], acc[k][3]);
    }
}

// ---------------------------------------------------------------------------
extern "C" void kernel_launch(void* const* d_in, const int* in_sizes, int n_in,
                              void* d_out, int out_size) {
    (void)in_sizes; (void)n_in; (void)out_size;
    const float* pts = (const float*)d_in[0];
    const float* kr  = (const float*)d_in[1];
    const float* ki  = (const float*)d_in[2];
    const float* wl  = (const float*)d_in[3];
    float* out = (float*)d_out;

    const int sm1 = (16384 + 512) * (int)sizeof(float);                       // 66 KB
    const int sm5 = (4096 + 1280 + 1280 + 512 + 256*SPS) * (int)sizeof(float); // ~94 KB
    cudaFuncSetAttribute(k_fwd_w, cudaFuncAttributeMaxDynamicSharedMemorySize, sm1);
    cudaFuncSetAttribute(k_final, cudaFuncAttributeMaxDynamicSharedMemorySize, sm5);

    // K1 split into two half-batch launches (keeps the ncu capture slot on
    // k_mix for direct before/after evidence on change #2).
    k_fwd_w<<<dim3(Hh, Bb/2), 320, sm1>>>(pts, 0);
    k_fwd_w<<<dim3(Hh, Bb/2), 320, sm1>>>(pts, Bb/2);
    k_fwd_h<<<dim3(M2m, Bb, 2), 128>>>();
    k_mix  <<<dim3(M1m*M2m, 2), 256>>>(kr, ki);
    k_inv_h<<<dim3(M2m, Bb, 2), 256>>>();
    k_final<<<dim3(Hh, Bb), 256, sm5>>>(pts, wl, out);
}

// round 15
// speedup vs baseline: 1.0095x; 1.0095x over previous
#include <cuda_runtime.h>
#include <cstdint>

#define Bb 16
#define Hh 256
#define Ww 256
#define Cc 64
#define M1m 20
#define M2m 20

// Scratch (device globals; no allocation allowed)
__device__ float2 g_A [Bb*Hh*M2m*Cc];   // forward w-transform   [b][h][ky][c]
__device__ float2 g_M [Bb*M2m*M1m*Cc];  // K2 partial (h-chunk 0)
__device__ float2 g_Mo[Bb*M2m*M1m*Cc];  // K2 partial (chunk 1) -> then mixed modes
__device__ float2 g_T [Bb*Hh*M2m*Cc];   // inverse h-expand      [b][h][ky][c]

#define TWO_PI_OVER_256 0.0245436926061702596f

// ---- f32x2 helpers ----------------------------------------------------------
__device__ __forceinline__ double ffma2(double a, double b, double c) {
    double d;
    asm("fma.rn.f32x2 %0, %1, %2, %3;" : "=d"(d) : "d"(a), "d"(b), "d"(c));
    return d;
}
__device__ __forceinline__ double add2(double a, double b) {
    double d;
    asm("add.rn.f32x2 %0, %1, %2;" : "=d"(d) : "d"(a), "d"(b));
    return d;
}
__device__ __forceinline__ double neg2(double a) {
    return __longlong_as_double(__double_as_longlong(a) ^ 0x8000000080000000ULL);
}
__device__ __forceinline__ double dup2(float x) {
    double d; asm("mov.b64 %0, {%1, %1};" : "=d"(d) : "f"(x)); return d;
}
__device__ __forceinline__ float2 up2(double d) {
    float2 f; asm("mov.b64 {%0, %1}, %2;" : "=f"(f.x), "=f"(f.y) : "d"(d));
    return f;
}
__device__ __forceinline__ uint32_t smem_u32(const void* p) {
    uint32_t a;
    asm("{ .reg .u64 t; cvta.to.shared.u64 t, %1; cvt.u32.u64 %0, t; }"
        : "=r"(a) : "l"(p));
    return a;
}
__device__ __forceinline__ void cp_async8(uint32_t dst, const void* src) {
    asm volatile("cp.async.ca.shared.global [%0], [%1], 8;"
                 :: "r"(dst), "l"(src) : "memory");
}

// ---------------------------------------------------------------------------
// K1: A[b,h,ky,c] = sum_w P*e^{-i ky w th}   (mod-4 radix fold over w)
// [round-10 proven fused LDG->FADD->STS fill; b0 = batch offset for split]
// ---------------------------------------------------------------------------
__global__ void __launch_bounds__(320) k_fwd_w(const float* __restrict__ pts,
                                               int b0) {
    extern __shared__ float sm[];
    float*  sS0 = sm;                        // [64][64]
    float*  sS2 = sm + 4096;
    float*  sDr = sm + 8192;
    float*  sDi = sm + 12288;
    float2* tcs = (float2*)(sm + 16384);     // 256 x (cos, -sin)
    const int h = blockIdx.x, b = blockIdx.y + b0;
    const int tid = threadIdx.x;
    const float4* prow = (const float4*)(pts + ((size_t)(b*Hh + h))*(Ww*Cc));
    for (int i = tid; i < 1024; i += 320) {
        float4 a = prow[i], e = prow[i+1024], c = prow[i+2048], d = prow[i+3072];
        float4 pac = make_float4(a.x+c.x, a.y+c.y, a.z+c.z, a.w+c.w);
        float4 pbd = make_float4(e.x+d.x, e.y+d.y, e.z+d.z, e.w+d.w);
        ((float4*)sS0)[i] = make_float4(pac.x+pbd.x, pac.y+pbd.y,
                                        pac.z+pbd.z, pac.w+pbd.w);
        ((float4*)sS2)[i] = make_float4(pac.x-pbd.x, pac.y-pbd.y,
                                        pac.z-pbd.z, pac.w-pbd.w);
        ((float4*)sDr)[i] = make_float4(a.x-c.x, a.y-c.y, a.z-c.z, a.w-c.w);
        ((float4*)sDi)[i] = make_float4(e.x-d.x, e.y-d.y, e.z-d.z, e.w-d.w);
    }
    if (tid < 256) {
        float s, c; sincosf((float)tid * TWO_PI_OVER_256, &s, &c);
        tcs[tid] = make_float2(c, -s);
    }
    __syncthreads();

    const int ws = tid & 1;
    const int cg = (tid >> 1) & 7;
    const int idx = tid >> 4;                 // 0..19
    const int c0 = cg * 8;
    const int wbeg = ws * 32;

    float r[8], q[8];
    int ky;

    if (idx < 10) {                           // even ky class
        ky = 2 * idx;
        const float* plane = (ky & 2) ? sS2 : sS0;
        #pragma unroll
        for (int k = 0; k < 8; ++k) { r[k] = 0.f; q[k] = 0.f; }
        int t = (ky * wbeg) & 255;
        #pragma unroll 4
        for (int w = wbeg; w < wbeg + 32; ++w) {
            const float* pr = plane + w*64 + c0;
            float4 pA = *(const float4*)(pr);
            float4 pB = *(const float4*)(pr + 4);
            float2 cs = tcs[t];
            float cv = cs.x, ns = cs.y;
            r[0] += pA.x*cv; q[0] += pA.x*ns;
            r[1] += pA.y*cv; q[1] += pA.y*ns;
            r[2] += pA.z*cv; q[2] += pA.z*ns;
            r[3] += pA.w*cv; q[3] += pA.w*ns;
            r[4] += pB.x*cv; q[4] += pB.x*ns;
            r[5] += pB.y*cv; q[5] += pB.y*ns;
            r[6] += pB.z*cv; q[6] += pB.z*ns;
            r[7] += pB.w*cv; q[7] += pB.w*ns;
            t = (t + ky) & 255;
        }
    } else {                                  // odd ky class
        ky = 2 * (idx - 10) + 1;
        float xr[8], xs[8], yc[8], yn[8];
        #pragma unroll
        for (int k = 0; k < 8; ++k) { xr[k]=0.f; xs[k]=0.f; yc[k]=0.f; yn[k]=0.f; }
        int t = (ky * wbeg) & 255;
        #pragma unroll 2
        for (int w = wbeg; w < wbeg + 32; ++w) {
            const float* drp = sDr + w*64 + c0;
            const float* dip = sDi + w*64 + c0;
            float4 rA = *(const float4*)(drp);
            float4 rB = *(const float4*)(drp + 4);
            float4 iA = *(const float4*)(dip);
            float4 iB = *(const float4*)(dip + 4);
            float2 cs = tcs[t];
            float cv = cs.x, ns = cs.y;
            xr[0] += rA.x*cv; xs[0] += rA.x*ns; yc[0] += iA.x*cv; yn[0] += iA.x*ns;
            xr[1] += rA.y*cv; xs[1] += rA.y*ns; yc[1] += iA.y*cv; yn[1] += iA.y*ns;
            xr[2] += rA.z*cv; xs[2] += rA.z*ns; yc[2] += iA.z*cv; yn[2] += iA.z*ns;
            xr[3] += rA.w*cv; xs[3] += rA.w*ns; yc[3] += iA.w*cv; yn[3] += iA.w*ns;
            xr[4] += rB.x*cv; xs[4] += rB.x*ns; yc[4] += iB.x*cv; yn[4] += iB.x*ns;
            xr[5] += rB.y*cv; xs[5] += rB.y*ns; yc[5] += iB.y*cv; yn[5] += iB.y*ns;
            xr[6] += rB.z*cv; xs[6] += rB.z*ns; yc[6] += iB.z*cv; yn[6] += iB.z*ns;
            xr[7] += rB.w*cv; xs[7] += rB.w*ns; yc[7] += iB.w*cv; yn[7] += iB.w*ns;
            t = (t + ky) & 255;
        }
        const float s = ((ky & 3) == 1) ? -1.f : 1.f;
        #pragma unroll
        for (int k = 0; k < 8; ++k) {
            r[k] = xr[k] - s*yn[k];
            q[k] = xs[k] + s*yc[k];
        }
    }

    __syncthreads();
    if (ws == 1) {
        float* buf = sS0 + (ky*8 + cg)*16;
        #pragma unroll
        for (int k = 0; k < 8; ++k) { buf[k] = r[k]; buf[8+k] = q[k]; }
    }
    __syncthreads();
    if (ws == 0) {
        const float* buf = sS0 + (ky*8 + cg)*16;
        #pragma unroll
        for (int k = 0; k < 8; ++k) { r[k] += buf[k]; q[k] += buf[8+k]; }
        float2* dst = g_A + (((size_t)(b*Hh + h))*M2m + ky)*Cc + c0;
        #pragma unroll
        for (int k = 0; k < 4; ++k)
            *(float4*)(dst + 2*k) = make_float4(r[2*k], q[2*k], r[2*k+1], q[2*k+1]);
    }
}

// ---------------------------------------------------------------------------
// K2: M[b,ky,kx,c] = sum_h A*e^{-i(kx-10)h th}   (mod-2 fold, 2-way h split)
// [round-10 proven version]
// ---------------------------------------------------------------------------
#define HT2 32
__global__ void __launch_bounds__(128) k_fwd_h() {
    __shared__ float2 sAp[HT2*Cc];
    __shared__ float2 sAm[HT2*Cc];
    __shared__ float sCv[HT2*M1m];
    __shared__ float sSv[HT2*M1m];
    __shared__ float2 tbl[256];
    const int ky = blockIdx.x, b = blockIdx.y, hc = blockIdx.z;
    const int tid = threadIdx.x;
    for (int i = tid; i < 256; i += 128) {
        float s, c; sincosf((float)i * TWO_PI_OVER_256, &s, &c);
        tbl[i] = make_float2(c, s);
    }
    const int cc = tid & 63, kg = tid >> 6;
    double aar[5] = {0,0,0,0,0}, aai[5] = {0,0,0,0,0};
    __syncthreads();

    for (int h0 = hc*64; h0 < hc*64 + 64; h0 += HT2) {
        __syncthreads();
        for (int i = tid; i < HT2*Cc; i += 128) {
            int hh = i >> 6, c = i & 63;
            float2 a0 = g_A[(((size_t)(b*Hh + h0 + hh))*M2m + ky)*Cc + c];
            float2 a1 = g_A[(((size_t)(b*Hh + h0 + hh + 128))*M2m + ky)*Cc + c];
            sAp[i] = make_float2(a0.x + a1.x, a0.y + a1.y);
            sAm[i] = make_float2(a0.x - a1.x, a0.y - a1.y);
        }
        for (int i = tid; i < HT2*M1m; i += 128) {
            int hh = i / M1m, jj = i - hh*M1m;
            int kgg = jj / 10, j = jj - kgg*10;
            int kx = 2*j + kgg;
            float2 cs = tbl[((kx + 246) * (h0 + hh)) & 255];
            sCv[i] = cs.x; sSv[i] = cs.y;
        }
        __syncthreads();
        const float2* plane = kg ? sAm : sAp;
        #pragma unroll 2
        for (int hh = 0; hh < HT2; ++hh) {
            float2 a = plane[hh*Cc + cc];
            double dax = dup2(a.x), day = dup2(a.y), dnx = dup2(-a.x);
            const float* cvp = sCv + hh*M1m + kg*10;
            const float* svp = sSv + hh*M1m + kg*10;
            #pragma unroll
            for (int p = 0; p < 5; ++p) {
                double cp = *(const double*)(cvp + 2*p);
                double sp = *(const double*)(svp + 2*p);
                aar[p] = ffma2(dax, cp, aar[p]);
                aar[p] = ffma2(day, sp, aar[p]);
                aai[p] = ffma2(day, cp, aai[p]);
                aai[p] = ffma2(dnx, sp, aai[p]);
            }
        }
    }
    float2* gout = hc ? g_Mo : g_M;
    #pragma unroll
    for (int p = 0; p < 5; ++p) {
        float2 r = up2(aar[p]), im = up2(aai[p]);
        int kx0 = 4*p + kg;
        size_t base = (((size_t)(b*M2m + ky))*M1m)*Cc + cc;
        gout[base + (size_t)kx0*Cc]       = make_float2(r.x, im.x);
        gout[base + (size_t)(kx0+2)*Cc]   = make_float2(r.y, im.y);
    }
}

// ---------------------------------------------------------------------------
// K3: channel mix + alpha fold; input = g_M + g_Mo partials, output -> g_Mo
// grid (400, 2) -> 800 CTAs  [round-14 measured win: 21.6 -> 19.4us]
// ---------------------------------------------------------------------------
__global__ void __launch_bounds__(256) k_mix(const float* __restrict__ kr,
                                             const float* __restrict__ ki) {
    __shared__ float sKr[64*65];
    __shared__ float sKi[64*65];
    __shared__ float2 sMin[8*64];
    const int kx = blockIdx.x / M2m, ky = blockIdx.x % M2m;
    const int bh = blockIdx.y;
    const int tid = threadIdx.x;
    const size_t kbase = ((size_t)(kx*M2m + ky))*Cc*Cc;
    for (int idx = tid; idx < 64*64; idx += 256) {
        int i = idx >> 6, j = idx & 63;
        sKr[i*65 + j] = kr[kbase + idx];
        sKi[i*65 + j] = ki[kbase + idx];
    }
    for (int idx = tid; idx < 8*64; idx += 256) {
        int bb = bh*8 + (idx >> 6), j = idx & 63;
        size_t gi = (((size_t)(bb*M2m + ky))*M1m + kx)*Cc + j;
        float2 m0 = g_M[gi], m1 = g_Mo[gi];
        sMin[idx] = make_float2(m0.x + m1.x, m0.y + m1.y);
    }
    __syncthreads();
    const float sc = (ky == 0 ? 1.0f : 2.0f) * (1.0f/65536.0f);
    const int i = tid & 63, bq = tid >> 6;
    float ar[2] = {0,0}, ai[2] = {0,0};
    for (int j = 0; j < 64; ++j) {
        float krv = sKr[i*65 + j], kiv = sKi[i*65 + j];
        #pragma unroll
        for (int r = 0; r < 2; ++r) {
            float2 m = sMin[(bq*2 + r)*64 + j];
            ar[r] += krv*m.x - kiv*m.y;
            ai[r] += krv*m.y + kiv*m.x;
        }
    }
    #pragma unroll
    for (int r = 0; r < 2; ++r) {
        int bb = bh*8 + bq*2 + r;
        g_Mo[(((size_t)(bb*M2m + ky))*M1m + kx)*Cc + i] =
            make_float2(ar[r]*sc, ai[r]*sc);
    }
}

// ---------------------------------------------------------------------------
// K4: T[b,h,ky,c] = sum_kx Mo*e^{+i(kx-10)h th}   (mod-2 fold over h)
// [round-10 proven version]
// ---------------------------------------------------------------------------
__global__ void __launch_bounds__(256) k_inv_h() {
    __shared__ float2 sMo[M1m*Cc];
    __shared__ float2 tA[256];
    __shared__ float2 tB[256];
    const int ky = blockIdx.x, b = blockIdx.y, hc = blockIdx.z;
    const int tid = threadIdx.x;
    {
        float s, c; sincosf((float)tid * TWO_PI_OVER_256, &s, &c);
        tA[tid] = make_float2(c, s);
        tB[tid] = make_float2(-s, c);
    }
    for (int i = tid; i < M1m*Cc; i += 256)
        sMo[i] = g_Mo[((size_t)(b*M2m + ky))*M1m*Cc + i];
    __syncthreads();
    const int cc = tid & 63, hg = tid >> 6;
    double dmr[M1m], dmi[M1m];
    #pragma unroll
    for (int kx = 0; kx < M1m; ++kx) {
        float2 m = sMo[kx*Cc + cc];
        dmr[kx] = dup2(m.x); dmi[kx] = dup2(m.y);
    }
    #pragma unroll 2
    for (int it = 0; it < 16; ++it) {
        int h = hc*64 + hg + 4*it;
        double ae = 0.0, ao = 0.0;
        int t = (246*h) & 255;
        #pragma unroll
        for (int kx = 0; kx < M1m; ++kx) {
            double ta = *(const double*)&tA[t];
            double tb = *(const double*)&tB[t];
            if (kx & 1) {
                ao = ffma2(dmr[kx], ta, ao);
                ao = ffma2(dmi[kx], tb, ao);
            } else {
                ae = ffma2(dmr[kx], ta, ae);
                ae = ffma2(dmi[kx], tb, ae);
            }
            t = (t + h) & 255;
        }
        float2 fe = up2(ae), fo = up2(ao);
        size_t base = (((size_t)(b*Hh + h))*M2m + ky)*Cc + cc;
        g_T[base]                       = make_float2(fe.x + fo.x, fe.y + fo.y);
        g_T[base + (size_t)128*M2m*Cc]  = make_float2(fe.x - fo.x, fe.y - fo.y);
    }
}

// ---------------------------------------------------------------------------
// K5: out[w,c] = spectral + P @ (Wl^T + I)   [round-13 proven: cp.async fill]
// ---------------------------------------------------------------------------
#define SPS 66
__global__ void __launch_bounds__(256, 2) k_final(const float* __restrict__ pts,
                                                  const float* __restrict__ wl,
                                                  float* __restrict__ out) {
    extern __shared__ float sm[];
    float*  sW  = sm;                        // [j][c] 64x64 (wl^T + I)
    float*  sTe = sm + 4096;                 // [10][128] even ky: Tr | -Ti
    float*  sTo = sTe + 1280;                // [10][128] odd ky
    float2* tcs = (float2*)(sTo + 1280);     // 256 (cos, sin)
    float*  sP  = (float*)(tcs + 256);       // [256][SPS]
    const int h = blockIdx.x, b = blockIdx.y;
    const int tid = threadIdx.x;
    const size_t rowbase = ((size_t)(b*Hh + h))*(Ww*Cc);

    // ---- sP fill via cp.async, issued first (no register dependency) ----
    {
        const float* srcbase = pts + rowbase;
        const uint32_t sPa = smem_u32(sP);
        for (int i = tid; i < 4096; i += 256) {
            int row = i >> 4, c4 = (i & 15) << 2;
            uint32_t dst = sPa + (uint32_t)(row*SPS + c4) * 4u;
            const float* src = srcbase + i*4;
            cp_async8(dst, src);
            cp_async8(dst + 8, src + 2);
        }
        asm volatile("cp.async.commit_group;" ::: "memory");
    }

    // ---- other fills (normal) ----
    for (int idx = tid; idx < Cc*Cc; idx += 256) {
        int c = idx >> 6, j = idx & 63;
        sW[j*64 + c] = wl[idx] + ((c == j) ? 1.0f : 0.0f);
    }
    {
        const float2* tsrc = g_T + ((size_t)(b*Hh + h))*M2m*Cc;
        for (int i = tid; i < M2m*Cc; i += 256) {
            int ky = i >> 6, c = i & 63;
            float2 v = tsrc[i];
            float* basep = (ky & 1) ? sTo : sTe;
            int e = ky >> 1;
            basep[e*128 + c]      = v.x;
            basep[e*128 + 64 + c] = -v.y;
        }
    }
    {
        float s, c; sincosf((float)tid * TWO_PI_OVER_256, &s, &c);
        tcs[tid] = make_float2(c, s);
    }
    __syncthreads();   // sTe/sTo/tcs/sW ready; sP still in flight

    const int cg = tid & 7, wpg = tid >> 3;
    const int c0 = cg * 8;
    const int wbase = wpg * 4;

    double acc[8][4];   // [k<4: rows wbase+k][4+k: +128 mirrors] x 4 c-pairs

    // ---- spectral (overlaps cp.async landing) ----
    #pragma unroll
    for (int pass = 0; pass < 2; ++pass) {
        const int wb0 = wbase + pass*2;
        double Re[2][4], Ro[2][4];
        #pragma unroll
        for (int pp = 0; pp < 2; ++pp)
            #pragma unroll
            for (int cp = 0; cp < 4; ++cp) { Re[pp][cp] = 0.0; Ro[pp][cp] = 0.0; }

        #pragma unroll
        for (int e = 0; e < 10; ++e) {          // even ky = 2e
            const float* row = sTe + e*128;
            double2 t0 = *(const double2*)(row + c0);
            double2 t1 = *(const double2*)(row + c0 + 4);
            double2 n0 = *(const double2*)(row + 64 + c0);
            double2 n1 = *(const double2*)(row + 68 + c0);
            #pragma unroll
            for (int pp = 0; pp < 2; ++pp) {
                float2 cs = tcs[(2*e*(wb0+pp)) & 255];
                double dc = dup2(cs.x), ds = dup2(cs.y);
                Re[pp][0] = ffma2(dc, t0.x, Re[pp][0]);
                Re[pp][1] = ffma2(dc, t0.y, Re[pp][1]);
                Re[pp][2] = ffma2(dc, t1.x, Re[pp][2]);
                Re[pp][3] = ffma2(dc, t1.y, Re[pp][3]);
                Re[pp][0] = ffma2(ds, n0.x, Re[pp][0]);
                Re[pp][1] = ffma2(ds, n0.y, Re[pp][1]);
                Re[pp][2] = ffma2(ds, n1.x, Re[pp][2]);
                Re[pp][3] = ffma2(ds, n1.y, Re[pp][3]);
            }
        }
        #pragma unroll
        for (int e = 0; e < 10; ++e) {          // odd ky = 2e+1
            const float* row = sTo + e*128;
            double2 t0 = *(const double2*)(row + c0);
            double2 t1 = *(const double2*)(row + c0 + 4);
            double2 n0 = *(const double2*)(row + 64 + c0);
            double2 n1 = *(const double2*)(row + 68 + c0);
            #pragma unroll
            for (int pp = 0; pp < 2; ++pp) {
                float2 cs = tcs[((2*e+1)*(wb0+pp)) & 255];
                double dc = dup2(cs.x), ds = dup2(cs.y);
                Ro[pp][0] = ffma2(dc, t0.x, Ro[pp][0]);
                Ro[pp][1] = ffma2(dc, t0.y, Ro[pp][1]);
                Ro[pp][2] = ffma2(dc, t1.x, Ro[pp][2]);
                Ro[pp][3] = ffma2(dc, t1.y, Ro[pp][3]);
                Ro[pp][0] = ffma2(ds, n0.x, Ro[pp][0]);
                Ro[pp][1] = ffma2(ds, n0.y, Ro[pp][1]);
                Ro[pp][2] = ffma2(ds, n1.x, Ro[pp][2]);
                Ro[pp][3] = ffma2(ds, n1.y, Ro[pp][3]);
            }
        }
        #pragma unroll
        for (int pp = 0; pp < 2; ++pp) {
            int k = pass*2 + pp;
            #pragma unroll
            for (int cp = 0; cp < 4; ++cp) {
                acc[k][cp]     = add2(Re[pp][cp], Ro[pp][cp]);
                acc[4 + k][cp] = add2(Re[pp][cp], neg2(Ro[pp][cp]));
            }
        }
    }

    // ---- wait for sP, then linear GEMM ----
    asm volatile("cp.async.wait_group 0;" ::: "memory");
    __syncthreads();

    #pragma unroll 2
    for (int j = 0; j < Cc; j += 2) {
        double2 B0a = *(const double2*)(sW + (j+0)*64 + c0);
        double2 B0b = *(const double2*)(sW + (j+0)*64 + c0 + 4);
        double2 B1a = *(const double2*)(sW + (j+1)*64 + c0);
        double2 B1b = *(const double2*)(sW + (j+1)*64 + c0 + 4);
        #pragma unroll
        for (int k = 0; k < 8; ++k) {
            int row = (k < 4) ? (wbase + k) : (wbase + k - 4 + 128);
            float2 p = *(const float2*)(sP + row*SPS + j);
            double d0 = dup2(p.x), d1 = dup2(p.y);
            acc[k][0] = ffma2(d0, B0a.x, acc[k][0]);
            acc[k][1] = ffma2(d0, B0a.y, acc[k][1]);
            acc[k][2] = ffma2(d0, B0b.x, acc[k][2]);
            acc[k][3] = ffma2(d0, B0b.y, acc[k][3]);
            acc[k][0] = ffma2(d1, B1a.x, acc[k][0]);
            acc[k][1] = ffma2(d1, B1a.y, acc[k][1]);
            acc[k][2] = ffma2(d1, B1b.x, acc[k][2]);
            acc[k][3] = ffma2(d1, B1b.y, acc[k][3]);
        }
    }

    // ---- store (double2 = packed float pairs, bit-exact layout) ----
    #pragma unroll
    for (int k = 0; k < 8; ++k) {
        int row = (k < 4) ? (wbase + k) : (wbase + k - 4 + 128);
        float* op = out + rowbase + (size_t)row*Cc + c0;
        *(double2*)(op)     = make_double2(acc[k][0], acc[k][1]);
        *(double2*)(op + 4) = make_double2(acc[k][2], acc[k][3]);
    }
}

// ---------------------------------------------------------------------------
extern "C" void kernel_launch(void* const* d_in, const int* in_sizes, int n_in,
                              void* d_out, int out_size) {
    (void)in_sizes; (void)n_in; (void)out_size;
    const float* pts = (const float*)d_in[0];
    const float* kr  = (const float*)d_in[1];
    const float* ki  = (const float*)d_in[2];
    const float* wl  = (const float*)d_in[3];
    float* out = (float*)d_out;

    const int sm1 = (16384 + 512) * (int)sizeof(float);                       // 66 KB
    const int sm5 = (4096 + 1280 + 1280 + 512 + 256*SPS) * (int)sizeof(float); // ~94 KB
    cudaFuncSetAttribute(k_fwd_w, cudaFuncAttributeMaxDynamicSharedMemorySize, sm1);
    cudaFuncSetAttribute(k_final, cudaFuncAttributeMaxDynamicSharedMemorySize, sm5);

    // K1 split into two half-batch launches (perf-neutral; keeps the ncu
    // capture slot on k_mix for direct before/after evidence).
    k_fwd_w<<<dim3(Hh, Bb/2), 320, sm1>>>(pts, 0);
    k_fwd_w<<<dim3(Hh, Bb/2), 320, sm1>>>(pts, Bb/2);
    k_fwd_h<<<dim3(M2m, Bb, 2), 128>>>();
    k_mix  <<<dim3(M1m*M2m, 2), 256>>>(kr, ki);
    k_inv_h<<<dim3(M2m, Bb, 2), 256>>>();
    k_final<<<dim3(Hh, Bb), 256, sm5>>>(pts, wl, out);
}

// round 16
// speedup vs baseline: 1.0239x; 1.0143x over previous
#include <cuda_runtime.h>
#include <cstdint>

#define Bb 16
#define Hh 256
#define Ww 256
#define Cc 64
#define M1m 20
#define M2m 20

// Scratch (device globals; no allocation allowed)
__device__ float2 g_A [Bb*Hh*M2m*Cc];   // forward w-transform   [b][h][ky][c]
__device__ float2 g_M [Bb*M2m*M1m*Cc];  // K2 partial (h-chunk 0)
__device__ float2 g_Mo[Bb*M2m*M1m*Cc];  // K2 partial (chunk 1) -> then mixed modes
__device__ float2 g_T [Bb*Hh*M2m*Cc];   // inverse h-expand      [b][h][ky][c]

#define TWO_PI_OVER_256 0.0245436926061702596f

// ---- f32x2 helpers ----------------------------------------------------------
__device__ __forceinline__ double ffma2(double a, double b, double c) {
    double d;
    asm("fma.rn.f32x2 %0, %1, %2, %3;" : "=d"(d) : "d"(a), "d"(b), "d"(c));
    return d;
}
__device__ __forceinline__ double add2(double a, double b) {
    double d;
    asm("add.rn.f32x2 %0, %1, %2;" : "=d"(d) : "d"(a), "d"(b));
    return d;
}
__device__ __forceinline__ double neg2(double a) {
    return __longlong_as_double(__double_as_longlong(a) ^ 0x8000000080000000ULL);
}
__device__ __forceinline__ double dup2(float x) {
    double d; asm("mov.b64 %0, {%1, %1};" : "=d"(d) : "f"(x)); return d;
}
__device__ __forceinline__ float2 up2(double d) {
    float2 f; asm("mov.b64 {%0, %1}, %2;" : "=f"(f.x), "=f"(f.y) : "d"(d));
    return f;
}
__device__ __forceinline__ uint32_t smem_u32(const void* p) {
    uint32_t a;
    asm("{ .reg .u64 t; cvta.to.shared.u64 t, %1; cvt.u32.u64 %0, t; }"
        : "=r"(a) : "l"(p));
    return a;
}
__device__ __forceinline__ void cp_async8(uint32_t dst, const void* src) {
    asm volatile("cp.async.ca.shared.global [%0], [%1], 8;"
                 :: "r"(dst), "l"(src) : "memory");
}

// ---------------------------------------------------------------------------
// K1: A[b,h,ky,c] = sum_w P*e^{-i ky w th}   (mod-4 radix fold over w)
// [round-10 proven fused LDG->FADD->STS fill; b0 = batch offset for split]
// ---------------------------------------------------------------------------
__global__ void __launch_bounds__(320) k_fwd_w(const float* __restrict__ pts,
                                               int b0) {
    extern __shared__ float sm[];
    float*  sS0 = sm;                        // [64][64]
    float*  sS2 = sm + 4096;
    float*  sDr = sm + 8192;
    float*  sDi = sm + 12288;
    float2* tcs = (float2*)(sm + 16384);     // 256 x (cos, -sin)
    const int h = blockIdx.x, b = blockIdx.y + b0;
    const int tid = threadIdx.x;
    const float4* prow = (const float4*)(pts + ((size_t)(b*Hh + h))*(Ww*Cc));
    for (int i = tid; i < 1024; i += 320) {
        float4 a = prow[i], e = prow[i+1024], c = prow[i+2048], d = prow[i+3072];
        float4 pac = make_float4(a.x+c.x, a.y+c.y, a.z+c.z, a.w+c.w);
        float4 pbd = make_float4(e.x+d.x, e.y+d.y, e.z+d.z, e.w+d.w);
        ((float4*)sS0)[i] = make_float4(pac.x+pbd.x, pac.y+pbd.y,
                                        pac.z+pbd.z, pac.w+pbd.w);
        ((float4*)sS2)[i] = make_float4(pac.x-pbd.x, pac.y-pbd.y,
                                        pac.z-pbd.z, pac.w-pbd.w);
        ((float4*)sDr)[i] = make_float4(a.x-c.x, a.y-c.y, a.z-c.z, a.w-c.w);
        ((float4*)sDi)[i] = make_float4(e.x-d.x, e.y-d.y, e.z-d.z, e.w-d.w);
    }
    if (tid < 256) {
        float s, c; sincosf((float)tid * TWO_PI_OVER_256, &s, &c);
        tcs[tid] = make_float2(c, -s);
    }
    __syncthreads();

    const int ws = tid & 1;
    const int cg = (tid >> 1) & 7;
    const int idx = tid >> 4;                 // 0..19
    const int c0 = cg * 8;
    const int wbeg = ws * 32;

    float r[8], q[8];
    int ky;

    if (idx < 10) {                           // even ky class
        ky = 2 * idx;
        const float* plane = (ky & 2) ? sS2 : sS0;
        #pragma unroll
        for (int k = 0; k < 8; ++k) { r[k] = 0.f; q[k] = 0.f; }
        int t = (ky * wbeg) & 255;
        #pragma unroll 4
        for (int w = wbeg; w < wbeg + 32; ++w) {
            const float* pr = plane + w*64 + c0;
            float4 pA = *(const float4*)(pr);
            float4 pB = *(const float4*)(pr + 4);
            float2 cs = tcs[t];
            float cv = cs.x, ns = cs.y;
            r[0] += pA.x*cv; q[0] += pA.x*ns;
            r[1] += pA.y*cv; q[1] += pA.y*ns;
            r[2] += pA.z*cv; q[2] += pA.z*ns;
            r[3] += pA.w*cv; q[3] += pA.w*ns;
            r[4] += pB.x*cv; q[4] += pB.x*ns;
            r[5] += pB.y*cv; q[5] += pB.y*ns;
            r[6] += pB.z*cv; q[6] += pB.z*ns;
            r[7] += pB.w*cv; q[7] += pB.w*ns;
            t = (t + ky) & 255;
        }
    } else {                                  // odd ky class
        ky = 2 * (idx - 10) + 1;
        float xr[8], xs[8], yc[8], yn[8];
        #pragma unroll
        for (int k = 0; k < 8; ++k) { xr[k]=0.f; xs[k]=0.f; yc[k]=0.f; yn[k]=0.f; }
        int t = (ky * wbeg) & 255;
        #pragma unroll 2
        for (int w = wbeg; w < wbeg + 32; ++w) {
            const float* drp = sDr + w*64 + c0;
            const float* dip = sDi + w*64 + c0;
            float4 rA = *(const float4*)(drp);
            float4 rB = *(const float4*)(drp + 4);
            float4 iA = *(const float4*)(dip);
            float4 iB = *(const float4*)(dip + 4);
            float2 cs = tcs[t];
            float cv = cs.x, ns = cs.y;
            xr[0] += rA.x*cv; xs[0] += rA.x*ns; yc[0] += iA.x*cv; yn[0] += iA.x*ns;
            xr[1] += rA.y*cv; xs[1] += rA.y*ns; yc[1] += iA.y*cv; yn[1] += iA.y*ns;
            xr[2] += rA.z*cv; xs[2] += rA.z*ns; yc[2] += iA.z*cv; yn[2] += iA.z*ns;
            xr[3] += rA.w*cv; xs[3] += rA.w*ns; yc[3] += iA.w*cv; yn[3] += iA.w*ns;
            xr[4] += rB.x*cv; xs[4] += rB.x*ns; yc[4] += iB.x*cv; yn[4] += iB.x*ns;
            xr[5] += rB.y*cv; xs[5] += rB.y*ns; yc[5] += iB.y*cv; yn[5] += iB.y*ns;
            xr[6] += rB.z*cv; xs[6] += rB.z*ns; yc[6] += iB.z*cv; yn[6] += iB.z*ns;
            xr[7] += rB.w*cv; xs[7] += rB.w*ns; yc[7] += iB.w*cv; yn[7] += iB.w*ns;
            t = (t + ky) & 255;
        }
        const float s = ((ky & 3) == 1) ? -1.f : 1.f;
        #pragma unroll
        for (int k = 0; k < 8; ++k) {
            r[k] = xr[k] - s*yn[k];
            q[k] = xs[k] + s*yc[k];
        }
    }

    __syncthreads();
    if (ws == 1) {
        float* buf = sS0 + (ky*8 + cg)*16;
        #pragma unroll
        for (int k = 0; k < 8; ++k) { buf[k] = r[k]; buf[8+k] = q[k]; }
    }
    __syncthreads();
    if (ws == 0) {
        const float* buf = sS0 + (ky*8 + cg)*16;
        #pragma unroll
        for (int k = 0; k < 8; ++k) { r[k] += buf[k]; q[k] += buf[8+k]; }
        float2* dst = g_A + (((size_t)(b*Hh + h))*M2m + ky)*Cc + c0;
        #pragma unroll
        for (int k = 0; k < 4; ++k)
            *(float4*)(dst + 2*k) = make_float4(r[2*k], q[2*k], r[2*k+1], q[2*k+1]);
    }
}

// ---------------------------------------------------------------------------
// K2: M[b,ky,kx,c] = sum_h A*e^{-i(kx-10)h th}   (mod-2 fold, 2-way h split)
// [round-10 proven version]
// ---------------------------------------------------------------------------
#define HT2 32
__global__ void __launch_bounds__(128) k_fwd_h() {
    __shared__ float2 sAp[HT2*Cc];
    __shared__ float2 sAm[HT2*Cc];
    __shared__ float sCv[HT2*M1m];
    __shared__ float sSv[HT2*M1m];
    __shared__ float2 tbl[256];
    const int ky = blockIdx.x, b = blockIdx.y, hc = blockIdx.z;
    const int tid = threadIdx.x;
    for (int i = tid; i < 256; i += 128) {
        float s, c; sincosf((float)i * TWO_PI_OVER_256, &s, &c);
        tbl[i] = make_float2(c, s);
    }
    const int cc = tid & 63, kg = tid >> 6;
    double aar[5] = {0,0,0,0,0}, aai[5] = {0,0,0,0,0};
    __syncthreads();

    for (int h0 = hc*64; h0 < hc*64 + 64; h0 += HT2) {
        __syncthreads();
        for (int i = tid; i < HT2*Cc; i += 128) {
            int hh = i >> 6, c = i & 63;
            float2 a0 = g_A[(((size_t)(b*Hh + h0 + hh))*M2m + ky)*Cc + c];
            float2 a1 = g_A[(((size_t)(b*Hh + h0 + hh + 128))*M2m + ky)*Cc + c];
            sAp[i] = make_float2(a0.x + a1.x, a0.y + a1.y);
            sAm[i] = make_float2(a0.x - a1.x, a0.y - a1.y);
        }
        for (int i = tid; i < HT2*M1m; i += 128) {
            int hh = i / M1m, jj = i - hh*M1m;
            int kgg = jj / 10, j = jj - kgg*10;
            int kx = 2*j + kgg;
            float2 cs = tbl[((kx + 246) * (h0 + hh)) & 255];
            sCv[i] = cs.x; sSv[i] = cs.y;
        }
        __syncthreads();
        const float2* plane = kg ? sAm : sAp;
        #pragma unroll 2
        for (int hh = 0; hh < HT2; ++hh) {
            float2 a = plane[hh*Cc + cc];
            double dax = dup2(a.x), day = dup2(a.y), dnx = dup2(-a.x);
            const float* cvp = sCv + hh*M1m + kg*10;
            const float* svp = sSv + hh*M1m + kg*10;
            #pragma unroll
            for (int p = 0; p < 5; ++p) {
                double cp = *(const double*)(cvp + 2*p);
                double sp = *(const double*)(svp + 2*p);
                aar[p] = ffma2(dax, cp, aar[p]);
                aar[p] = ffma2(day, sp, aar[p]);
                aai[p] = ffma2(day, cp, aai[p]);
                aai[p] = ffma2(dnx, sp, aai[p]);
            }
        }
    }
    float2* gout = hc ? g_Mo : g_M;
    #pragma unroll
    for (int p = 0; p < 5; ++p) {
        float2 r = up2(aar[p]), im = up2(aai[p]);
        int kx0 = 4*p + kg;
        size_t base = (((size_t)(b*M2m + ky))*M1m)*Cc + cc;
        gout[base + (size_t)kx0*Cc]       = make_float2(r.x, im.x);
        gout[base + (size_t)(kx0+2)*Cc]   = make_float2(r.y, im.y);
    }
}

// ---------------------------------------------------------------------------
// K3: channel mix + alpha fold; input = g_M + g_Mo partials, output -> g_Mo
// grid (400, 2) -> 800 CTAs  [round-14 measured win]
// ---------------------------------------------------------------------------
__global__ void __launch_bounds__(256) k_mix(const float* __restrict__ kr,
                                             const float* __restrict__ ki) {
    __shared__ float sKr[64*65];
    __shared__ float sKi[64*65];
    __shared__ float2 sMin[8*64];
    const int kx = blockIdx.x / M2m, ky = blockIdx.x % M2m;
    const int bh = blockIdx.y;
    const int tid = threadIdx.x;
    const size_t kbase = ((size_t)(kx*M2m + ky))*Cc*Cc;
    for (int idx = tid; idx < 64*64; idx += 256) {
        int i = idx >> 6, j = idx & 63;
        sKr[i*65 + j] = kr[kbase + idx];
        sKi[i*65 + j] = ki[kbase + idx];
    }
    for (int idx = tid; idx < 8*64; idx += 256) {
        int bb = bh*8 + (idx >> 6), j = idx & 63;
        size_t gi = (((size_t)(bb*M2m + ky))*M1m + kx)*Cc + j;
        float2 m0 = g_M[gi], m1 = g_Mo[gi];
        sMin[idx] = make_float2(m0.x + m1.x, m0.y + m1.y);
    }
    __syncthreads();
    const float sc = (ky == 0 ? 1.0f : 2.0f) * (1.0f/65536.0f);
    const int i = tid & 63, bq = tid >> 6;
    float ar[2] = {0,0}, ai[2] = {0,0};
    for (int j = 0; j < 64; ++j) {
        float krv = sKr[i*65 + j], kiv = sKi[i*65 + j];
        #pragma unroll
        for (int r = 0; r < 2; ++r) {
            float2 m = sMin[(bq*2 + r)*64 + j];
            ar[r] += krv*m.x - kiv*m.y;
            ai[r] += krv*m.y + kiv*m.x;
        }
    }
    #pragma unroll
    for (int r = 0; r < 2; ++r) {
        int bb = bh*8 + bq*2 + r;
        g_Mo[(((size_t)(bb*M2m + ky))*M1m + kx)*Cc + i] =
            make_float2(ar[r]*sc, ai[r]*sc);
    }
}

// ---------------------------------------------------------------------------
// K4: T[b,h,ky,c] = sum_kx Mo*e^{+i(kx-10)h th}   (mod-2 fold over h)
// [round-10 proven version]
// ---------------------------------------------------------------------------
__global__ void __launch_bounds__(256) k_inv_h() {
    __shared__ float2 sMo[M1m*Cc];
    __shared__ float2 tA[256];
    __shared__ float2 tB[256];
    const int ky = blockIdx.x, b = blockIdx.y, hc = blockIdx.z;
    const int tid = threadIdx.x;
    {
        float s, c; sincosf((float)tid * TWO_PI_OVER_256, &s, &c);
        tA[tid] = make_float2(c, s);
        tB[tid] = make_float2(-s, c);
    }
    for (int i = tid; i < M1m*Cc; i += 256)
        sMo[i] = g_Mo[((size_t)(b*M2m + ky))*M1m*Cc + i];
    __syncthreads();
    const int cc = tid & 63, hg = tid >> 6;
    double dmr[M1m], dmi[M1m];
    #pragma unroll
    for (int kx = 0; kx < M1m; ++kx) {
        float2 m = sMo[kx*Cc + cc];
        dmr[kx] = dup2(m.x); dmi[kx] = dup2(m.y);
    }
    #pragma unroll 2
    for (int it = 0; it < 16; ++it) {
        int h = hc*64 + hg + 4*it;
        double ae = 0.0, ao = 0.0;
        int t = (246*h) & 255;
        #pragma unroll
        for (int kx = 0; kx < M1m; ++kx) {
            double ta = *(const double*)&tA[t];
            double tb = *(const double*)&tB[t];
            if (kx & 1) {
                ao = ffma2(dmr[kx], ta, ao);
                ao = ffma2(dmi[kx], tb, ao);
            } else {
                ae = ffma2(dmr[kx], ta, ae);
                ae = ffma2(dmi[kx], tb, ae);
            }
            t = (t + h) & 255;
        }
        float2 fe = up2(ae), fo = up2(ao);
        size_t base = (((size_t)(b*Hh + h))*M2m + ky)*Cc + cc;
        g_T[base]                       = make_float2(fe.x + fo.x, fe.y + fo.y);
        g_T[base + (size_t)128*M2m*Cc]  = make_float2(fe.x - fo.x, fe.y - fo.y);
    }
}

// ---------------------------------------------------------------------------
// K5: out[w,c] = spectral + P @ (Wl^T + I)   [cp.async fill + mod-4 spectral]
// mod-4 over w: thread owns base rows wb0,wb0+1 (w<64) and images +64/128/192.
//   even ky: S0 (ky%4==0), S2 (ky%4==2); images combine as S0+-S2.
//   odd ky:  C = sum(Tr*cos + nTi*sin), D = sum(s4*(Tr*sin - nTi*cos)),
//            s4 = -1 (ky%4==1), +1 (ky%4==3); images: +C,+D,-C,-D.
// Spectral FFMA2: 640 -> 480/thread; transient regs shrink 32 -> 16 doubles.
// ---------------------------------------------------------------------------
#define SPS 66
__global__ void __launch_bounds__(256, 2) k_final(const float* __restrict__ pts,
                                                  const float* __restrict__ wl,
                                                  float* __restrict__ out) {
    extern __shared__ float sm[];
    float*  sW  = sm;                        // [j][c] 64x64 (wl^T + I)
    float*  sTe = sm + 4096;                 // [10][128] even ky: Tr | -Ti
    float*  sTo = sTe + 1280;                // [10][128] odd ky
    float2* tcs = (float2*)(sTo + 1280);     // 256 (cos, sin)
    float*  sP  = (float*)(tcs + 256);       // [256][SPS]
    const int h = blockIdx.x, b = blockIdx.y;
    const int tid = threadIdx.x;
    const size_t rowbase = ((size_t)(b*Hh + h))*(Ww*Cc);

    // ---- sP fill via cp.async, issued first (no register dependency) ----
    {
        const float* srcbase = pts + rowbase;
        const uint32_t sPa = smem_u32(sP);
        for (int i = tid; i < 4096; i += 256) {
            int row = i >> 4, c4 = (i & 15) << 2;
            uint32_t dst = sPa + (uint32_t)(row*SPS + c4) * 4u;
            const float* src = srcbase + i*4;
            cp_async8(dst, src);
            cp_async8(dst + 8, src + 2);
        }
        asm volatile("cp.async.commit_group;" ::: "memory");
    }

    // ---- other fills (normal) ----
    for (int idx = tid; idx < Cc*Cc; idx += 256) {
        int c = idx >> 6, j = idx & 63;
        sW[j*64 + c] = wl[idx] + ((c == j) ? 1.0f : 0.0f);
    }
    {
        const float2* tsrc = g_T + ((size_t)(b*Hh + h))*M2m*Cc;
        for (int i = tid; i < M2m*Cc; i += 256) {
            int ky = i >> 6, c = i & 63;
            float2 v = tsrc[i];
            float* basep = (ky & 1) ? sTo : sTe;
            int e = ky >> 1;
            basep[e*128 + c]      = v.x;
            basep[e*128 + 64 + c] = -v.y;
        }
    }
    {
        float s, c; sincosf((float)tid * TWO_PI_OVER_256, &s, &c);
        tcs[tid] = make_float2(c, s);
    }
    __syncthreads();   // sTe/sTo/tcs/sW ready; sP still in flight

    const int cg = tid & 7, wpg = tid >> 3;
    const int c0 = cg * 8;
    const int wb0 = wpg * 2;                 // base rows 0..63

    // acc[img*2 + pp][cp] : output row = wb0 + pp + 64*img
    double acc[8][4];

    // ---- spectral (overlaps cp.async landing); mod-4 folded ----
    #pragma unroll
    for (int pp = 0; pp < 2; ++pp) {
        const int r = wb0 + pp;

        // Phase A: even ky -> S0 (ky%4==0, e even), S2 (ky%4==2, e odd)
        double S0[4] = {0,0,0,0}, S2[4] = {0,0,0,0};
        #pragma unroll
        for (int e = 0; e < 10; ++e) {
            const float* row = sTe + e*128;
            double2 t0 = *(const double2*)(row + c0);
            double2 t1 = *(const double2*)(row + c0 + 4);
            double2 n0 = *(const double2*)(row + 64 + c0);
            double2 n1 = *(const double2*)(row + 68 + c0);
            float2 cs = tcs[(2*e*r) & 255];
            double dc = dup2(cs.x), ds = dup2(cs.y);
            if (e & 1) {
                S2[0] = ffma2(dc, t0.x, S2[0]); S2[0] = ffma2(ds, n0.x, S2[0]);
                S2[1] = ffma2(dc, t0.y, S2[1]); S2[1] = ffma2(ds, n0.y, S2[1]);
                S2[2] = ffma2(dc, t1.x, S2[2]); S2[2] = ffma2(ds, n1.x, S2[2]);
                S2[3] = ffma2(dc, t1.y, S2[3]); S2[3] = ffma2(ds, n1.y, S2[3]);
            } else {
                S0[0] = ffma2(dc, t0.x, S0[0]); S0[0] = ffma2(ds, n0.x, S0[0]);
                S0[1] = ffma2(dc, t0.y, S0[1]); S0[1] = ffma2(ds, n0.y, S0[1]);
                S0[2] = ffma2(dc, t1.x, S0[2]); S0[2] = ffma2(ds, n1.x, S0[2]);
                S0[3] = ffma2(dc, t1.y, S0[3]); S0[3] = ffma2(ds, n1.y, S0[3]);
            }
        }
        #pragma unroll
        for (int cp = 0; cp < 4; ++cp) {
            double A = add2(S0[cp], S2[cp]);
            double B = add2(S0[cp], neg2(S2[cp]));
            acc[0 + pp][cp] = A;
            acc[2 + pp][cp] = B;
            acc[4 + pp][cp] = A;
            acc[6 + pp][cp] = B;
        }

        // Phase B: odd ky -> C, D
        double Cs[4] = {0,0,0,0}, Ds[4] = {0,0,0,0};
        #pragma unroll
        for (int e = 0; e < 10; ++e) {
            const float* row = sTo + e*128;
            double2 t0 = *(const double2*)(row + c0);
            double2 t1 = *(const double2*)(row + c0 + 4);
            double2 n0 = *(const double2*)(row + 64 + c0);
            double2 n1 = *(const double2*)(row + 68 + c0);
            float2 cs = tcs[((2*e+1)*r) & 255];
            double dc = dup2(cs.x), ds = dup2(cs.y);
            // C += Tr*cos + nTi*sin
            Cs[0] = ffma2(dc, t0.x, Cs[0]); Cs[0] = ffma2(ds, n0.x, Cs[0]);
            Cs[1] = ffma2(dc, t0.y, Cs[1]); Cs[1] = ffma2(ds, n0.y, Cs[1]);
            Cs[2] = ffma2(dc, t1.x, Cs[2]); Cs[2] = ffma2(ds, n1.x, Cs[2]);
            Cs[3] = ffma2(dc, t1.y, Cs[3]); Cs[3] = ffma2(ds, n1.y, Cs[3]);
            // D += s4*(Tr*sin - nTi*cos); s4=-1 for e even (ky%4==1), +1 e odd
            float sv  = (e & 1) ? cs.y : -cs.y;
            float cv2 = (e & 1) ? -cs.x : cs.x;
            double dsv = dup2(sv), dcv = dup2(cv2);
            Ds[0] = ffma2(dsv, t0.x, Ds[0]); Ds[0] = ffma2(dcv, n0.x, Ds[0]);
            Ds[1] = ffma2(dsv, t0.y, Ds[1]); Ds[1] = ffma2(dcv, n0.y, Ds[1]);
            Ds[2] = ffma2(dsv, t1.x, Ds[2]); Ds[2] = ffma2(dcv, n1.x, Ds[2]);
            Ds[3] = ffma2(dsv, t1.y, Ds[3]); Ds[3] = ffma2(dcv, n1.y, Ds[3]);
        }
        #pragma unroll
        for (int cp = 0; cp < 4; ++cp) {
            acc[0 + pp][cp] = add2(acc[0 + pp][cp], Cs[cp]);
            acc[2 + pp][cp] = add2(acc[2 + pp][cp], Ds[cp]);
            acc[4 + pp][cp] = add2(acc[4 + pp][cp], neg2(Cs[cp]));
            acc[6 + pp][cp] = add2(acc[6 + pp][cp], neg2(Ds[cp]));
        }
    }

    // ---- wait for sP, then linear GEMM ----
    asm volatile("cp.async.wait_group 0;" ::: "memory");
    __syncthreads();

    #pragma unroll 2
    for (int j = 0; j < Cc; j += 2) {
        double2 B0a = *(const double2*)(sW + (j+0)*64 + c0);
        double2 B0b = *(const double2*)(sW + (j+0)*64 + c0 + 4);
        double2 B1a = *(const double2*)(sW + (j+1)*64 + c0);
        double2 B1b = *(const double2*)(sW + (j+1)*64 + c0 + 4);
        #pragma unroll
        for (int k = 0; k < 8; ++k) {
            int row = wb0 + (k & 1) + 64*(k >> 1);
            float2 p = *(const float2*)(sP + row*SPS + j);
            double d0 = dup2(p.x), d1 = dup2(p.y);
            acc[k][0] = ffma2(d0, B0a.x, acc[k][0]);
            acc[k][1] = ffma2(d0, B0a.y, acc[k][1]);
            acc[k][2] = ffma2(d0, B0b.x, acc[k][2]);
            acc[k][3] = ffma2(d0, B0b.y, acc[k][3]);
            acc[k][0] = ffma2(d1, B1a.x, acc[k][0]);
            acc[k][1] = ffma2(d1, B1a.y, acc[k][1]);
            acc[k][2] = ffma2(d1, B1b.x, acc[k][2]);
            acc[k][3] = ffma2(d1, B1b.y, acc[k][3]);
        }
    }

    // ---- store (double2 = packed float pairs, bit-exact layout) ----
    #pragma unroll
    for (int k = 0; k < 8; ++k) {
        int row = wb0 + (k & 1) + 64*(k >> 1);
        float* op = out + rowbase + (size_t)row*Cc + c0;
        *(double2*)(op)     = make_double2(acc[k][0], acc[k][1]);
        *(double2*)(op + 4) = make_double2(acc[k][2], acc[k][3]);
    }
}

// ---------------------------------------------------------------------------
extern "C" void kernel_launch(void* const* d_in, const int* in_sizes, int n_in,
                              void* d_out, int out_size) {
    (void)in_sizes; (void)n_in; (void)out_size;
    const float* pts = (const float*)d_in[0];
    const float* kr  = (const float*)d_in[1];
    const float* ki  = (const float*)d_in[2];
    const float* wl  = (const float*)d_in[3];
    float* out = (float*)d_out;

    const int sm1 = (16384 + 512) * (int)sizeof(float);                       // 66 KB
    const int sm5 = (4096 + 1280 + 1280 + 512 + 256*SPS) * (int)sizeof(float); // ~94 KB
    cudaFuncSetAttribute(k_fwd_w, cudaFuncAttributeMaxDynamicSharedMemorySize, sm1);
    cudaFuncSetAttribute(k_final, cudaFuncAttributeMaxDynamicSharedMemorySize, sm5);

    // K1 split into two half-batch launches (perf-neutral; keeps the ncu
    // capture slot on k_mix).
    k_fwd_w<<<dim3(Hh, Bb/2), 320, sm1>>>(pts, 0);
    k_fwd_w<<<dim3(Hh, Bb/2), 320, sm1>>>(pts, Bb/2);
    k_fwd_h<<<dim3(M2m, Bb, 2), 128>>>();
    k_mix  <<<dim3(M1m*M2m, 2), 256>>>(kr, ki);
    k_inv_h<<<dim3(M2m, Bb, 2), 256>>>();
    k_final<<<dim3(Hh, Bb), 256, sm5>>>(pts, wl, out);
}